// round 2
// baseline (speedup 1.0000x reference)
#include <cuda_runtime.h>
#include <math.h>

// FullAttention: B=4, L=S=2048, H=8, E=D=64, fp32.
// out[b,l,h,d] = softmax_s( (1/sqrt(E)) * Q[b,l,h,:]·K[b,s,h,:] ) · V[b,s,h,:]
//
// Flash-attention style single pass: each CTA owns a 64-row Q tile for one
// (b,h); iterates over S in 64-wide chunks with online softmax.
// 256 threads as 16x16; each thread owns a 4x4 register sub-tile.

#define BM 64
#define BN 64
#define EDIM 64
#define DDIM 64
#define LDP 65   // padded leading dim (64+1) -> conflict-free LDS

static constexpr int Bb = 4;
static constexpr int Ll = 2048;
static constexpr int Ss = 2048;
static constexpr int Hh = 8;

__global__ __launch_bounds__(256, 3)
void flash_fwd_f32(const float* __restrict__ Q,
                   const float* __restrict__ K,
                   const float* __restrict__ V,
                   float* __restrict__ Out)
{
    extern __shared__ float smem[];
    float* sQ = smem;                 // [BM][LDP]
    float* sK = sQ + BM * LDP;        // [BN][LDP]
    float* sV = sK + BN * LDP;        // [BN][LDP]
    float* sP = sV + BN * LDP;        // [BM][LDP]

    const int tid = threadIdx.x;
    const int tx  = tid & 15;         // col group
    const int ty  = tid >> 4;         // row group

    const int qtile = blockIdx.x;     // L / BM tiles
    const int h     = blockIdx.y;
    const int b     = blockIdx.z;

    const int q0 = qtile * BM;

    // Row stride (in floats) between consecutive l (or s) positions: H*E
    const int gstride = Hh * EDIM;    // 512

    const float* Qbase = Q + ((size_t)(b * Ll + q0) * Hh + h) * EDIM;
    const float* Kbase = K + ((size_t)(b * Ss) * Hh + h) * EDIM;
    const float* Vbase = V + ((size_t)(b * Ss) * Hh + h) * DDIM;

    // ---- Load Q tile (64 x 64 floats), float4 from gmem, scalar to padded smem
    {
        // 1024 float4 total, 256 threads, 4 iters
        #pragma unroll
        for (int it = 0; it < 4; it++) {
            int idx  = it * 256 + tid;        // 0..1023
            int row  = idx >> 4;              // 16 float4 per row
            int c4   = idx & 15;
            const float4 v = *reinterpret_cast<const float4*>(
                Qbase + (size_t)row * gstride + c4 * 4);
            float* dst = sQ + row * LDP + c4 * 4;
            dst[0] = v.x; dst[1] = v.y; dst[2] = v.z; dst[3] = v.w;
        }
    }

    // Per-thread state: 4 query rows (ty + 16*i), 4 out cols (tx + 16*j)
    float o[4][4];
    float m_run[4], l_run[4];
    #pragma unroll
    for (int i = 0; i < 4; i++) {
        m_run[i] = -INFINITY;
        l_run[i] = 0.0f;
        #pragma unroll
        for (int j = 0; j < 4; j++) o[i][j] = 0.0f;
    }

    const float scale = 0.125f;  // 1/sqrt(64)

    for (int s0 = 0; s0 < Ss; s0 += BN) {
        __syncthreads();  // previous PV GEMM done before overwriting sK/sV

        // ---- Load K,V tiles
        #pragma unroll
        for (int it = 0; it < 4; it++) {
            int idx  = it * 256 + tid;
            int row  = idx >> 4;
            int c4   = idx & 15;
            const float4 kv = *reinterpret_cast<const float4*>(
                Kbase + (size_t)(s0 + row) * gstride + c4 * 4);
            float* kd = sK + row * LDP + c4 * 4;
            kd[0] = kv.x; kd[1] = kv.y; kd[2] = kv.z; kd[3] = kv.w;
            const float4 vv = *reinterpret_cast<const float4*>(
                Vbase + (size_t)(s0 + row) * gstride + c4 * 4);
            float* vd = sV + row * LDP + c4 * 4;
            vd[0] = vv.x; vd[1] = vv.y; vd[2] = vv.z; vd[3] = vv.w;
        }
        __syncthreads();

        // ---- GEMM1: s[i][j] = Q[r_i,:] . K[c_j,:]
        float acc[4][4];
        #pragma unroll
        for (int i = 0; i < 4; i++)
            #pragma unroll
            for (int j = 0; j < 4; j++) acc[i][j] = 0.0f;

        #pragma unroll 8
        for (int k = 0; k < EDIM; k++) {
            float qv[4], kv[4];
            #pragma unroll
            for (int i = 0; i < 4; i++) qv[i] = sQ[(ty + 16 * i) * LDP + k];
            #pragma unroll
            for (int j = 0; j < 4; j++) kv[j] = sK[(tx + 16 * j) * LDP + k];
            #pragma unroll
            for (int i = 0; i < 4; i++)
                #pragma unroll
                for (int j = 0; j < 4; j++)
                    acc[i][j] = fmaf(qv[i], kv[j], acc[i][j]);
        }

        // ---- Online softmax (rows owned by 16 threads sharing ty; reduce over tx)
        float p[4][4];
        float alpha[4];
        #pragma unroll
        for (int i = 0; i < 4; i++) {
            float mm = -INFINITY;
            #pragma unroll
            for (int j = 0; j < 4; j++) {
                acc[i][j] *= scale;
                mm = fmaxf(mm, acc[i][j]);
            }
            // reduce max across the 16-thread tx group (within 16-lane half-warp)
            #pragma unroll
            for (int off = 8; off >= 1; off >>= 1)
                mm = fmaxf(mm, __shfl_xor_sync(0xffffffffu, mm, off));

            float m_new = fmaxf(m_run[i], mm);
            alpha[i] = __expf(m_run[i] - m_new);   // 0 on first tile (m_run=-inf)
            float rs = 0.0f;
            #pragma unroll
            for (int j = 0; j < 4; j++) {
                p[i][j] = __expf(acc[i][j] - m_new);
                rs += p[i][j];
            }
            #pragma unroll
            for (int off = 8; off >= 1; off >>= 1)
                rs += __shfl_xor_sync(0xffffffffu, rs, off);

            l_run[i] = l_run[i] * alpha[i] + rs;
            m_run[i] = m_new;
            #pragma unroll
            for (int j = 0; j < 4; j++) o[i][j] *= alpha[i];
        }

        // ---- Stage P to smem for the PV GEMM
        #pragma unroll
        for (int i = 0; i < 4; i++)
            #pragma unroll
            for (int j = 0; j < 4; j++)
                sP[(ty + 16 * i) * LDP + (tx + 16 * j)] = p[i][j];
        __syncthreads();

        // ---- GEMM2: o[i][j] += sum_s P[r_i][s] * V[s][c_j]
        #pragma unroll 8
        for (int s = 0; s < BN; s++) {
            float pv[4], vv[4];
            #pragma unroll
            for (int i = 0; i < 4; i++) pv[i] = sP[(ty + 16 * i) * LDP + s];
            #pragma unroll
            for (int j = 0; j < 4; j++) vv[j] = sV[s * LDP + (tx + 16 * j)];
            #pragma unroll
            for (int i = 0; i < 4; i++)
                #pragma unroll
                for (int j = 0; j < 4; j++)
                    o[i][j] = fmaf(pv[i], vv[j], o[i][j]);
        }
    }

    // ---- Epilogue: normalize and write out[b, q0+r, h, d]
    #pragma unroll
    for (int i = 0; i < 4; i++) {
        const float inv_l = 1.0f / l_run[i];
        const int qr = q0 + ty + 16 * i;
        float* obase = Out + ((size_t)(b * Ll + qr) * Hh + h) * DDIM;
        #pragma unroll
        for (int j = 0; j < 4; j++)
            obase[tx + 16 * j] = o[i][j] * inv_l;
    }
}

extern "C" void kernel_launch(void* const* d_in, const int* in_sizes, int n_in,
                              void* d_out, int out_size)
{
    const float* Q = (const float*)d_in[0];
    const float* K = (const float*)d_in[1];
    const float* V = (const float*)d_in[2];
    float* Out = (float*)d_out;

    const int smem_bytes = 4 * BM * LDP * sizeof(float);  // 66560 B
    cudaFuncSetAttribute(flash_fwd_f32,
                         cudaFuncAttributeMaxDynamicSharedMemorySize, smem_bytes);

    dim3 grid(Ll / BM, Hh, Bb);   // (32, 8, 4) — x-fastest keeps (b,h) CTAs adjacent for L2 K/V reuse
    flash_fwd_f32<<<grid, 256, smem_bytes>>>(Q, K, V, Out);
}

// round 3
// speedup vs baseline: 3.6698x; 3.6698x over previous
#include <cuda_runtime.h>
#include <math.h>
#include <stdint.h>

// FullAttention B=4, L=S=2048, H=8, E=D=64, fp32 in/out.
// Flash-attention, tensor cores via mma.sync.m16n8k8 tf32.
// CTA = 128 threads (4 warps), Q tile 64 rows (16 per warp), KV chunk 64.

#define BM 64
#define BN 64
#define LDQ 68   // Q/K/P stride: A/B-frag pattern bank = 4*(l/4)+(l%4) -> conflict-free
#define LDK 68
#define LDV 72   // V stride: B-frag pattern bank = 8*(l%4)+(l/4) -> conflict-free
#define LDPD 68

static constexpr int Bb = 4, Ll = 2048, Ss = 2048, Hh = 8, Ee = 64, Dd = 64;

__device__ __forceinline__ uint32_t f2tf32(float f) {
    uint32_t u;
    asm("cvt.rna.tf32.f32 %0, %1;" : "=r"(u) : "f"(f));
    return u;
}

__device__ __forceinline__ void mma_tf32(float* c,
                                         uint32_t a0, uint32_t a1, uint32_t a2, uint32_t a3,
                                         uint32_t b0, uint32_t b1) {
    asm volatile(
        "mma.sync.aligned.m16n8k8.row.col.f32.tf32.tf32.f32 "
        "{%0,%1,%2,%3}, {%4,%5,%6,%7}, {%8,%9}, {%0,%1,%2,%3};"
        : "+f"(c[0]), "+f"(c[1]), "+f"(c[2]), "+f"(c[3])
        : "r"(a0), "r"(a1), "r"(a2), "r"(a3), "r"(b0), "r"(b1));
}

__global__ __launch_bounds__(128, 3)
void flash_tf32(const float* __restrict__ Q, const float* __restrict__ K,
                const float* __restrict__ V, float* __restrict__ Out)
{
    extern __shared__ uint32_t smem[];
    uint32_t* sQ = smem;                  // [BM][LDQ]  tf32 bits (pre-scaled)
    uint32_t* sK = sQ + BM * LDQ;         // [BN][LDK]
    uint32_t* sV = sK + BN * LDK;         // [BN][LDV]
    uint32_t* sP = sV + BN * LDV;         // [BM][LDPD]

    const int tid  = threadIdx.x;
    const int lane = tid & 31;
    const int warp = tid >> 5;
    const int ty4  = lane >> 2;   // 0..7
    const int tx4  = lane & 3;    // 0..3
    const int mbase = warp * 16;  // warp's Q-row base within tile

    const int qtile = blockIdx.x, h = blockIdx.y, b = blockIdx.z;
    const int q0 = qtile * BM;
    const int gstride = Hh * Ee;  // 512 floats between consecutive l/s

    const float* Qbase = Q + ((size_t)(b * Ll + q0) * Hh + h) * Ee;
    const float* Kbase = K + ((size_t)b * Ss * Hh + h) * Ee;
    const float* Vbase = V + ((size_t)b * Ss * Hh + h) * Dd;

    const float scale = 0.125f;  // 1/sqrt(64), folded into Q

    // ---- Load Q tile (scaled, tf32-rounded). 1024 float4, 128 threads, 8 iters.
    #pragma unroll
    for (int it = 0; it < 8; it++) {
        int idx = it * 128 + tid;
        int row = idx >> 4, c4 = idx & 15;
        float4 v = *reinterpret_cast<const float4*>(Qbase + (size_t)row * gstride + c4 * 4);
        uint4 w;
        w.x = f2tf32(v.x * scale); w.y = f2tf32(v.y * scale);
        w.z = f2tf32(v.z * scale); w.w = f2tf32(v.w * scale);
        *reinterpret_cast<uint4*>(&sQ[row * LDQ + c4 * 4]) = w;
    }

    // O accumulators: 8 d-tiles x 4 (C-frag). Rows: ty4 and ty4+8.
    float acc_o[8][4];
    float m_run[2] = {-INFINITY, -INFINITY};
    float l_run[2] = {0.f, 0.f};
    #pragma unroll
    for (int n = 0; n < 8; n++)
        #pragma unroll
        for (int j = 0; j < 4; j++) acc_o[n][j] = 0.f;

    for (int s0 = 0; s0 < Ss; s0 += BN) {
        __syncthreads();  // prior iteration's reads of sK/sV/sP done

        // ---- Load K,V chunk (tf32-rounded)
        #pragma unroll
        for (int it = 0; it < 8; it++) {
            int idx = it * 128 + tid;
            int row = idx >> 4, c4 = idx & 15;
            float4 kv = *reinterpret_cast<const float4*>(Kbase + (size_t)(s0 + row) * gstride + c4 * 4);
            uint4 kw;
            kw.x = f2tf32(kv.x); kw.y = f2tf32(kv.y); kw.z = f2tf32(kv.z); kw.w = f2tf32(kv.w);
            *reinterpret_cast<uint4*>(&sK[row * LDK + c4 * 4]) = kw;
            float4 vv = *reinterpret_cast<const float4*>(Vbase + (size_t)(s0 + row) * gstride + c4 * 4);
            uint4 vw;
            vw.x = f2tf32(vv.x); vw.y = f2tf32(vv.y); vw.z = f2tf32(vv.z); vw.w = f2tf32(vv.w);
            *reinterpret_cast<uint4*>(&sV[row * LDV + c4 * 4]) = vw;
        }
        __syncthreads();

        // ---- S = Q @ K^T : 8 k-steps x 8 n-tiles of m16n8k8
        float acc[8][4];
        #pragma unroll
        for (int n = 0; n < 8; n++)
            #pragma unroll
            for (int j = 0; j < 4; j++) acc[n][j] = 0.f;

        #pragma unroll
        for (int ks = 0; ks < 8; ks++) {
            const int k0 = ks * 8;
            uint32_t a0 = sQ[(mbase + ty4)     * LDQ + k0 + tx4];
            uint32_t a1 = sQ[(mbase + ty4 + 8) * LDQ + k0 + tx4];
            uint32_t a2 = sQ[(mbase + ty4)     * LDQ + k0 + tx4 + 4];
            uint32_t a3 = sQ[(mbase + ty4 + 8) * LDQ + k0 + tx4 + 4];
            #pragma unroll
            for (int n = 0; n < 8; n++) {
                uint32_t b0 = sK[(n * 8 + ty4) * LDK + k0 + tx4];       // B[k][n]=K[n][k]
                uint32_t b1 = sK[(n * 8 + ty4) * LDK + k0 + tx4 + 4];
                mma_tf32(acc[n], a0, a1, a2, a3, b0, b1);
            }
        }

        // ---- Online softmax. Thread owns rows (ty4, ty4+8); quad (xor 1,2) spans each row.
        float mx0 = -INFINITY, mx1 = -INFINITY;
        #pragma unroll
        for (int n = 0; n < 8; n++) {
            mx0 = fmaxf(mx0, fmaxf(acc[n][0], acc[n][1]));
            mx1 = fmaxf(mx1, fmaxf(acc[n][2], acc[n][3]));
        }
        mx0 = fmaxf(mx0, __shfl_xor_sync(0xffffffffu, mx0, 1));
        mx0 = fmaxf(mx0, __shfl_xor_sync(0xffffffffu, mx0, 2));
        mx1 = fmaxf(mx1, __shfl_xor_sync(0xffffffffu, mx1, 1));
        mx1 = fmaxf(mx1, __shfl_xor_sync(0xffffffffu, mx1, 2));

        const float mn0 = fmaxf(m_run[0], mx0);
        const float mn1 = fmaxf(m_run[1], mx1);
        const float al0 = __expf(m_run[0] - mn0);   // 0 on first tile
        const float al1 = __expf(m_run[1] - mn1);

        float sum0 = 0.f, sum1 = 0.f;
        #pragma unroll
        for (int n = 0; n < 8; n++) {
            float p0 = __expf(acc[n][0] - mn0);
            float p1 = __expf(acc[n][1] - mn0);
            float p2 = __expf(acc[n][2] - mn1);
            float p3 = __expf(acc[n][3] - mn1);
            sum0 += p0 + p1;
            sum1 += p2 + p3;
            uint2 lo; lo.x = f2tf32(p0); lo.y = f2tf32(p1);
            *reinterpret_cast<uint2*>(&sP[(mbase + ty4)     * LDPD + n * 8 + 2 * tx4]) = lo;
            uint2 hi; hi.x = f2tf32(p2); hi.y = f2tf32(p3);
            *reinterpret_cast<uint2*>(&sP[(mbase + ty4 + 8) * LDPD + n * 8 + 2 * tx4]) = hi;
        }
        sum0 += __shfl_xor_sync(0xffffffffu, sum0, 1);
        sum0 += __shfl_xor_sync(0xffffffffu, sum0, 2);
        sum1 += __shfl_xor_sync(0xffffffffu, sum1, 1);
        sum1 += __shfl_xor_sync(0xffffffffu, sum1, 2);

        l_run[0] = l_run[0] * al0 + sum0;  m_run[0] = mn0;
        l_run[1] = l_run[1] * al1 + sum1;  m_run[1] = mn1;

        #pragma unroll
        for (int n = 0; n < 8; n++) {
            acc_o[n][0] *= al0;  acc_o[n][1] *= al0;
            acc_o[n][2] *= al1;  acc_o[n][3] *= al1;
        }
        __syncwarp();  // P visible across the warp (own 16 rows only)

        // ---- O += P @ V : 8 k-steps x 8 d-tiles
        #pragma unroll
        for (int ks = 0; ks < 8; ks++) {
            const int k0 = ks * 8;
            uint32_t a0 = sP[(mbase + ty4)     * LDPD + k0 + tx4];
            uint32_t a1 = sP[(mbase + ty4 + 8) * LDPD + k0 + tx4];
            uint32_t a2 = sP[(mbase + ty4)     * LDPD + k0 + tx4 + 4];
            uint32_t a3 = sP[(mbase + ty4 + 8) * LDPD + k0 + tx4 + 4];
            #pragma unroll
            for (int n = 0; n < 8; n++) {
                uint32_t b0 = sV[(k0 + tx4)     * LDV + n * 8 + ty4];   // B[k][n]=V[k][n]
                uint32_t b1 = sV[(k0 + tx4 + 4) * LDV + n * 8 + ty4];
                mma_tf32(acc_o[n], a0, a1, a2, a3, b0, b1);
            }
        }
    }

    // ---- Epilogue: normalize, write Out[b, q0+row, h, d]
    const float inv0 = 1.f / l_run[0];
    const float inv1 = 1.f / l_run[1];
    const int r0 = q0 + mbase + ty4;
    const int r1 = r0 + 8;
    float* O0 = Out + ((size_t)(b * Ll + r0) * Hh + h) * Dd;
    float* O1 = Out + ((size_t)(b * Ll + r1) * Hh + h) * Dd;
    #pragma unroll
    for (int n = 0; n < 8; n++) {
        const int col = n * 8 + 2 * tx4;
        float2 v0; v0.x = acc_o[n][0] * inv0; v0.y = acc_o[n][1] * inv0;
        *reinterpret_cast<float2*>(O0 + col) = v0;
        float2 v1; v1.x = acc_o[n][2] * inv1; v1.y = acc_o[n][3] * inv1;
        *reinterpret_cast<float2*>(O1 + col) = v1;
    }
}

extern "C" void kernel_launch(void* const* d_in, const int* in_sizes, int n_in,
                              void* d_out, int out_size)
{
    const float* Q = (const float*)d_in[0];
    const float* K = (const float*)d_in[1];
    const float* V = (const float*)d_in[2];
    float* Out = (float*)d_out;

    const int smem_bytes = (BM * LDQ + BN * LDK + BN * LDV + BM * LDPD) * 4;  // 70656
    cudaFuncSetAttribute(flash_tf32,
                         cudaFuncAttributeMaxDynamicSharedMemorySize, smem_bytes);

    dim3 grid(Ll / BM, Hh, Bb);   // (32, 8, 4); x-fastest keeps same-(b,h) CTAs adjacent for L2 K/V reuse
    flash_tf32<<<grid, 128, smem_bytes>>>(Q, K, V, Out);
}